// round 3
// baseline (speedup 1.0000x reference)
#include <cuda_runtime.h>

#define IN_CH  512
#define KDIM   1024
#define OUT_CH 512
#define MAX_N  50000
#define MAX_E  800000

// ---------------- scratch (static device globals; no allocations) ----------------
__device__ int   g_count[MAX_N];
__device__ int   g_off[MAX_N + 1];
__device__ int   g_wptr[MAX_N];
__device__ int   g_csr[MAX_E];
__device__ float g_mean[(size_t)MAX_N * IN_CH];   // ~102 MB

// ---------------- CSR build ----------------
__global__ void zero_count_kernel(int n) {
    int i = blockIdx.x * blockDim.x + threadIdx.x;
    if (i < n) g_count[i] = 0;
}

__global__ void hist_kernel(const int* __restrict__ dst, int E, int n) {
    int e = blockIdx.x * blockDim.x + threadIdx.x;
    if (e < E) {
        int d = dst[e];
        if (d >= 0 && d < n) atomicAdd(&g_count[d], 1);
    }
}

// Single-block exclusive scan over n counts: warp-shuffle scan per 1024-chunk.
__global__ void scan_kernel(int n) {
    __shared__ int warp_sums[32];
    __shared__ int carry_s;
    int tid  = threadIdx.x;
    int lane = tid & 31;
    int wid  = tid >> 5;
    if (tid == 0) carry_s = 0;
    __syncthreads();

    for (int base = 0; base < n; base += 1024) {
        int i = base + tid;
        int v = (i < n) ? g_count[i] : 0;

        // intra-warp inclusive scan
        int s = v;
#pragma unroll
        for (int ofs = 1; ofs < 32; ofs <<= 1) {
            int t = __shfl_up_sync(0xFFFFFFFF, s, ofs);
            if (lane >= ofs) s += t;
        }
        if (lane == 31) warp_sums[wid] = s;
        __syncthreads();

        // scan warp sums with warp 0
        if (wid == 0) {
            int ws = (lane < 32) ? warp_sums[lane] : 0;
#pragma unroll
            for (int ofs = 1; ofs < 32; ofs <<= 1) {
                int t = __shfl_up_sync(0xFFFFFFFF, ws, ofs);
                if (lane >= ofs) ws += t;
            }
            warp_sums[lane] = ws;
        }
        __syncthreads();

        int warp_excl = (wid > 0) ? warp_sums[wid - 1] : 0;
        int incl = s + warp_excl;                 // inclusive within chunk
        int excl = incl - v + carry_s;
        if (i < n) { g_off[i] = excl; g_wptr[i] = excl; }
        __syncthreads();
        if (tid == 0) carry_s += warp_sums[31];
        __syncthreads();
    }
    if (threadIdx.x == 0) g_off[n] = carry_s;
}

__global__ void scatter_kernel(const int* __restrict__ src, const int* __restrict__ dst,
                               int E, int n) {
    int e = blockIdx.x * blockDim.x + threadIdx.x;
    if (e < E) {
        int d = dst[e];
        if (d >= 0 && d < n) {
            int p = atomicAdd(&g_wptr[d], 1);
            g_csr[p] = src[e];
        }
    }
}

// ---------------- aggregation: one block per node, register accumulation ----------------
__global__ void aggregate_kernel(const float* __restrict__ x) {
    int v = blockIdx.x;
    int t = threadIdx.x;                    // 128 threads, one float4 lane each
    int beg = g_off[v];
    int end = g_off[v + 1];
    const float4* __restrict__ x4 = (const float4*)x;
    float4 acc = make_float4(0.f, 0.f, 0.f, 0.f);

    int i = beg;
    for (; i + 4 <= end; i += 4) {
        int s0 = g_csr[i + 0];
        int s1 = g_csr[i + 1];
        int s2 = g_csr[i + 2];
        int s3 = g_csr[i + 3];
        float4 p0 = x4[(size_t)s0 * 128 + t];
        float4 p1 = x4[(size_t)s1 * 128 + t];
        float4 p2 = x4[(size_t)s2 * 128 + t];
        float4 p3 = x4[(size_t)s3 * 128 + t];
        acc.x += (p0.x + p1.x) + (p2.x + p3.x);
        acc.y += (p0.y + p1.y) + (p2.y + p3.y);
        acc.z += (p0.z + p1.z) + (p2.z + p3.z);
        acc.w += (p0.w + p1.w) + (p2.w + p3.w);
    }
    for (; i < end; i++) {
        int s = g_csr[i];
        float4 p = x4[(size_t)s * 128 + t];
        acc.x += p.x; acc.y += p.y; acc.z += p.z; acc.w += p.w;
    }

    int deg = end - beg;
    float inv = 1.0f / (float)(deg > 0 ? deg : 1);
    acc.x *= inv; acc.y *= inv; acc.z *= inv; acc.w *= inv;
    ((float4*)g_mean)[(size_t)v * 128 + t] = acc;
}

// ---------------- fused concat-GEMM: out = [x | mean] @ W^T + b ----------------
// 128x128 block tile, K-tile 8, 256 threads, 8x8 per-thread microtile.
// Software-pipelined: next K-tile's global loads issued before compute phase.
__global__ void __launch_bounds__(256, 2)
gemm_kernel(const float* __restrict__ x, const float* __restrict__ W,
            const float* __restrict__ bias, float* __restrict__ out, int M) {
    __shared__ float As[8][128];
    __shared__ float Bs[8][128];

    int bm  = blockIdx.x * 128;
    int bn  = blockIdx.y * 128;
    int tid = threadIdx.x;
    int tx  = tid & 15;    // n direction (16)
    int ty  = tid >> 4;    // m direction (16)

    float acc[8][8];
#pragma unroll
    for (int i = 0; i < 8; i++)
#pragma unroll
        for (int j = 0; j < 8; j++) acc[i][j] = 0.f;

    int ld_row = tid >> 1;          // 0..127
    int ld_col = (tid & 1) * 4;     // 0 or 4

    int m_a = bm + ld_row;          // A-load row for this thread (fixed)
    const float* b_base = W + (size_t)(bn + ld_row) * KDIM + ld_col;

    // ---- prologue: load K-tile 0 into registers ----
    float4 av = make_float4(0.f, 0.f, 0.f, 0.f);
    if (m_a < M) {
        const float* sp = (ld_col < IN_CH)
            ? (x      + (size_t)m_a * IN_CH + ld_col)
            : (g_mean + (size_t)m_a * IN_CH + (ld_col - IN_CH));
        av = *(const float4*)sp;
    }
    float4 bv = *(const float4*)(b_base);

    for (int k0 = 0; k0 < KDIM; k0 += 8) {
        // ---- commit prefetched tile to shared ----
        As[ld_col + 0][ld_row] = av.x;
        As[ld_col + 1][ld_row] = av.y;
        As[ld_col + 2][ld_row] = av.z;
        As[ld_col + 3][ld_row] = av.w;
        Bs[ld_col + 0][ld_row] = bv.x;
        Bs[ld_col + 1][ld_row] = bv.y;
        Bs[ld_col + 2][ld_row] = bv.z;
        Bs[ld_col + 3][ld_row] = bv.w;
        __syncthreads();

        // ---- issue next tile's global loads (overlap with compute) ----
        int kn = k0 + 8;
        if (kn < KDIM) {
            int kk = kn + ld_col;
            av = make_float4(0.f, 0.f, 0.f, 0.f);
            if (m_a < M) {
                const float* sp = (kk < IN_CH)
                    ? (x      + (size_t)m_a * IN_CH + kk)
                    : (g_mean + (size_t)m_a * IN_CH + (kk - IN_CH));
                av = *(const float4*)sp;
            }
            bv = *(const float4*)(b_base + kn);
        }

        // ---- compute on current smem tile ----
#pragma unroll
        for (int kk = 0; kk < 8; kk++) {
            float4 a0 = *(const float4*)&As[kk][ty * 8];
            float4 a1 = *(const float4*)&As[kk][ty * 8 + 4];
            float4 b0 = *(const float4*)&Bs[kk][tx * 8];
            float4 b1 = *(const float4*)&Bs[kk][tx * 8 + 4];
            float a[8] = {a0.x, a0.y, a0.z, a0.w, a1.x, a1.y, a1.z, a1.w};
            float b[8] = {b0.x, b0.y, b0.z, b0.w, b1.x, b1.y, b1.z, b1.w};
#pragma unroll
            for (int i = 0; i < 8; i++)
#pragma unroll
                for (int j = 0; j < 8; j++)
                    acc[i][j] += a[i] * b[j];
        }
        __syncthreads();
    }

    // ---- epilogue: + bias, vectorized store ----
#pragma unroll
    for (int i = 0; i < 8; i++) {
        int m = bm + ty * 8 + i;
        if (m >= M) continue;
#pragma unroll
        for (int jj = 0; jj < 8; jj += 4) {
            int n = bn + tx * 8 + jj;
            float4 o;
            o.x = acc[i][jj + 0] + bias[n + 0];
            o.y = acc[i][jj + 1] + bias[n + 1];
            o.z = acc[i][jj + 2] + bias[n + 2];
            o.w = acc[i][jj + 3] + bias[n + 3];
            *(float4*)(out + (size_t)m * OUT_CH + n) = o;
        }
    }
}

// ---------------- launch ----------------
extern "C" void kernel_launch(void* const* d_in, const int* in_sizes, int n_in,
                              void* d_out, int out_size) {
    const float* x    = (const float*)d_in[0];
    const int*   ei   = (const int*)d_in[1];
    const float* W    = (const float*)d_in[2];
    const float* bias = (const float*)d_in[3];
    float*       out  = (float*)d_out;

    int N = in_sizes[0] / IN_CH;      // 50000
    int E = in_sizes[1] / 2;          // 800000
    if (N <= 0 || N > MAX_N || E <= 0 || E > MAX_E) return;
    const int* src = ei;
    const int* dst = ei + E;

    zero_count_kernel<<<(N + 255) / 256, 256>>>(N);
    hist_kernel<<<(E + 255) / 256, 256>>>(dst, E, N);
    scan_kernel<<<1, 1024>>>(N);
    scatter_kernel<<<(E + 255) / 256, 256>>>(src, dst, E, N);
    aggregate_kernel<<<N, 128>>>(x);

    dim3 grid((N + 127) / 128, OUT_CH / 128);
    gemm_kernel<<<grid, 256>>>(x, W, bias, out, N);
}

// round 10
// speedup vs baseline: 1.8310x; 1.8310x over previous
#include <cuda_runtime.h>
#include <cuda_bf16.h>
#include <cstdint>

#define IN_CH  512
#define KDIM   1024
#define OUT_CH 512
#define MAX_N  50000
#define MAX_E  800000

// ---------------- scratch (static device globals; ~107 MB total) ----------------
__device__ int g_count[MAX_N];
__device__ int g_off[MAX_N + 1];
__device__ int g_wptr[MAX_N];
__device__ int g_csr[MAX_E];
__device__ __align__(16) float g_mean[(size_t)MAX_N * IN_CH];          // ~102 MB
__device__ __align__(16) __nv_bfloat16 g_Whi[(size_t)OUT_CH * KDIM];   // 1 MB
__device__ __align__(16) __nv_bfloat16 g_Wlo[(size_t)OUT_CH * KDIM];   // 1 MB

// ================= helpers =================
__device__ __forceinline__ uint32_t smem_u32(const void* p) {
    uint32_t a;
    asm("{ .reg .u64 t; cvta.to.shared.u64 t, %1; cvt.u32.u64 %0, t; }" : "=r"(a) : "l"(p));
    return a;
}
#define CP_ASYNC16(saddr, gptr) \
    asm volatile("cp.async.cg.shared.global [%0], [%1], 16;" :: "r"(saddr), "l"(gptr) : "memory")
#define CP_COMMIT() asm volatile("cp.async.commit_group;" ::: "memory")
#define CP_WAIT(N)  asm volatile("cp.async.wait_group %0;" :: "n"(N) : "memory")
#define LDMATRIX_X4(R, addr)                                                        \
    asm volatile("ldmatrix.sync.aligned.m8n8.x4.shared.b16 {%0,%1,%2,%3}, [%4];"    \
        : "=r"((R)[0]), "=r"((R)[1]), "=r"((R)[2]), "=r"((R)[3]) : "r"(addr))

__device__ __forceinline__ void mma_bf16(float* c, const uint32_t* a, uint32_t b0, uint32_t b1) {
    asm volatile(
        "mma.sync.aligned.m16n8k16.row.col.f32.bf16.bf16.f32 "
        "{%0,%1,%2,%3}, {%4,%5,%6,%7}, {%8,%9}, {%0,%1,%2,%3};"
        : "+f"(c[0]), "+f"(c[1]), "+f"(c[2]), "+f"(c[3])
        : "r"(a[0]), "r"(a[1]), "r"(a[2]), "r"(a[3]), "r"(b0), "r"(b1));
}

// ================= fp32 -> bf16 hi/lo split =================
__device__ __forceinline__ void split4(float4 v, uint2& hi, uint2& lo) {
    __nv_bfloat16 h0 = __float2bfloat16(v.x), h1 = __float2bfloat16(v.y);
    __nv_bfloat16 h2 = __float2bfloat16(v.z), h3 = __float2bfloat16(v.w);
    __nv_bfloat16 l0 = __float2bfloat16(v.x - __bfloat162float(h0));
    __nv_bfloat16 l1 = __float2bfloat16(v.y - __bfloat162float(h1));
    __nv_bfloat16 l2 = __float2bfloat16(v.z - __bfloat162float(h2));
    __nv_bfloat16 l3 = __float2bfloat16(v.w - __bfloat162float(h3));
    hi.x = ((uint32_t)__bfloat16_as_ushort(h1) << 16) | __bfloat16_as_ushort(h0);
    hi.y = ((uint32_t)__bfloat16_as_ushort(h3) << 16) | __bfloat16_as_ushort(h2);
    lo.x = ((uint32_t)__bfloat16_as_ushort(l1) << 16) | __bfloat16_as_ushort(l0);
    lo.y = ((uint32_t)__bfloat16_as_ushort(l3) << 16) | __bfloat16_as_ushort(l2);
}

// ================= CSR build =================
__global__ void zero_count_kernel(int n) {
    int i = blockIdx.x * blockDim.x + threadIdx.x;
    if (i < n) g_count[i] = 0;
}
__global__ void hist_kernel(const int* __restrict__ dst, int E, int n) {
    int e = blockIdx.x * blockDim.x + threadIdx.x;
    if (e < E) { int d = dst[e]; if (d >= 0 && d < n) atomicAdd(&g_count[d], 1); }
}
__global__ void scan_kernel(int n) {
    __shared__ int warp_sums[32];
    __shared__ int carry_s;
    int tid = threadIdx.x, lane = tid & 31, wid = tid >> 5;
    if (tid == 0) carry_s = 0;
    __syncthreads();
    for (int base = 0; base < n; base += 1024) {
        int i = base + tid;
        int v = (i < n) ? g_count[i] : 0;
        int s = v;
#pragma unroll
        for (int ofs = 1; ofs < 32; ofs <<= 1) {
            int t = __shfl_up_sync(0xFFFFFFFF, s, ofs);
            if (lane >= ofs) s += t;
        }
        if (lane == 31) warp_sums[wid] = s;
        __syncthreads();
        if (wid == 0) {
            int ws = warp_sums[lane];
#pragma unroll
            for (int ofs = 1; ofs < 32; ofs <<= 1) {
                int t = __shfl_up_sync(0xFFFFFFFF, ws, ofs);
                if (lane >= ofs) ws += t;
            }
            warp_sums[lane] = ws;
        }
        __syncthreads();
        int warp_excl = (wid > 0) ? warp_sums[wid - 1] : 0;
        int excl = s + warp_excl - v + carry_s;
        if (i < n) { g_off[i] = excl; g_wptr[i] = excl; }
        __syncthreads();
        if (tid == 0) carry_s += warp_sums[31];
        __syncthreads();
    }
    if (threadIdx.x == 0) g_off[n] = carry_s;
}
__global__ void scatter_kernel(const int* __restrict__ src, const int* __restrict__ dst,
                               int E, int n) {
    int e = blockIdx.x * blockDim.x + threadIdx.x;
    if (e < E) {
        int d = dst[e];
        if (d >= 0 && d < n) { int p = atomicAdd(&g_wptr[d], 1); g_csr[p] = src[e]; }
    }
}

// ================= aggregation: one block per node -> fp32 mean =================
__global__ void aggregate_kernel(const float* __restrict__ x) {
    int v = blockIdx.x;
    int t = threadIdx.x;                    // 128 threads, one float4 lane each
    int beg = g_off[v], end = g_off[v + 1];
    const float4* __restrict__ x4 = (const float4*)x;
    float4 acc = make_float4(0.f, 0.f, 0.f, 0.f);
    int i = beg;
    for (; i + 4 <= end; i += 4) {
        int s0 = g_csr[i + 0], s1 = g_csr[i + 1], s2 = g_csr[i + 2], s3 = g_csr[i + 3];
        float4 p0 = x4[(size_t)s0 * 128 + t];
        float4 p1 = x4[(size_t)s1 * 128 + t];
        float4 p2 = x4[(size_t)s2 * 128 + t];
        float4 p3 = x4[(size_t)s3 * 128 + t];
        acc.x += (p0.x + p1.x) + (p2.x + p3.x);
        acc.y += (p0.y + p1.y) + (p2.y + p3.y);
        acc.z += (p0.z + p1.z) + (p2.z + p3.z);
        acc.w += (p0.w + p1.w) + (p2.w + p3.w);
    }
    for (; i < end; i++) {
        int s = g_csr[i];
        float4 p = x4[(size_t)s * 128 + t];
        acc.x += p.x; acc.y += p.y; acc.z += p.z; acc.w += p.w;
    }
    int deg = end - beg;
    float inv = 1.0f / (float)(deg > 0 ? deg : 1);
    acc.x *= inv; acc.y *= inv; acc.z *= inv; acc.w *= inv;
    ((float4*)g_mean)[(size_t)v * 128 + t] = acc;
}

// ================= W convert (bf16 hi/lo) =================
__global__ void convert_w_kernel(const float* __restrict__ W) {
    int idx = blockIdx.x * blockDim.x + threadIdx.x;   // OUT_CH*256 threads
    if (idx >= OUT_CH * 256) return;
    int m = idx >> 8, t = idx & 255;
    float4 v = ((const float4*)W)[(size_t)m * 256 + t];
    uint2 hi, lo;
    split4(v, hi, lo);
    ((uint2*)(g_Whi + (size_t)m * KDIM))[t] = hi;
    ((uint2*)(g_Wlo + (size_t)m * KDIM))[t] = lo;
}

// ================= split-bf16 mma.sync GEMM: out = [x|mean] @ W^T + b =================
// CTA 128x128, K-tile 32, 8 warps (2m x 4n), warp tile 64x32.
// A: fp32 loaded from x/g_mean (fused concat), split to bf16 hi/lo in regs -> smem.
// B: bf16 hi/lo via cp.async, 2-stage double buffer.
#define ROWB      80                 // 32 bf16 = 64B data, 80B stride (bank-friendly)
#define ARR_BYTES (128 * ROWB)       // 10240
#define STAGE_BYTES (4 * ARR_BYTES)  // 40960
#define GSMEM_TOTAL (2 * STAGE_BYTES)

__device__ __forceinline__ float4 load_concatA(const float* __restrict__ x,
                                               int m, int kk, int N) {
    if (m >= N) return make_float4(0.f, 0.f, 0.f, 0.f);
    const float* p = (kk < IN_CH) ? (x      + (size_t)m * IN_CH + kk)
                                  : (g_mean + (size_t)m * IN_CH + (kk - IN_CH));
    return *(const float4*)p;
}

__device__ __forceinline__ void load_B_stage(uint32_t sb, int stage, int kofs,
                                             int bn, int tid) {
    uint32_t base = sb + stage * STAGE_BYTES;
#pragma unroll
    for (int i = 0; i < 2; i++) {
        int c = tid + i * 256;          // 0..511
        int row = c >> 2, j = c & 3;    // 4 x 16B per row
        uint32_t so = row * ROWB + j * 16;
        size_t gb = (size_t)(bn + row) * KDIM + kofs + j * 8;
        CP_ASYNC16(base + 2 * ARR_BYTES + so, (const char*)(g_Whi + gb));
        CP_ASYNC16(base + 3 * ARR_BYTES + so, (const char*)(g_Wlo + gb));
    }
}

__global__ void __launch_bounds__(256, 1)
gemm_mma_kernel(const float* __restrict__ x, const float* __restrict__ bias,
                float* __restrict__ out, int N) {
    extern __shared__ char smem[];
    uint32_t sb = smem_u32(smem);
    int tid = threadIdx.x, wid = tid >> 5, lane = tid & 31;
    int bm = blockIdx.x * 128;
    int bn = blockIdx.y * 128;
    int wm = (wid >> 2) * 64;     // warp m offset (0/64)
    int wn = (wid & 3) * 32;      // warp n offset (0/32/64/96)

    float acc[4][4][4];
#pragma unroll
    for (int mi = 0; mi < 4; mi++)
#pragma unroll
        for (int f = 0; f < 4; f++)
#pragma unroll
            for (int r = 0; r < 4; r++) acc[mi][f][r] = 0.f;

    // A loader: 128 rows x 32 fp32 = 1024 float4; 256 threads x 4.
    // c = tid + i*256: row = c>>3, j = c&7  (cols j*4 .. j*4+3)
    int a_row[4], a_j[4];
#pragma unroll
    for (int i = 0; i < 4; i++) {
        int c = tid + i * 256;
        a_row[i] = c >> 3;
        a_j[i]   = c & 7;
    }

    // ldmatrix per-thread source row/col-block
    int l8 = lane & 7, grp = lane >> 3;
    int ld_row = l8 + (grp & 1) * 8;
    int ld_kb  = (grp >> 1) * 8;

    // ---- prologue: A regs for kt=0, B stage 0 ----
    float4 apref[4];
#pragma unroll
    for (int i = 0; i < 4; i++)
        apref[i] = load_concatA(x, bm + a_row[i], a_j[i] * 4, N);
    load_B_stage(sb, 0, 0, bn, tid);
    CP_COMMIT();

    const int NT = KDIM / 32;   // 32
    for (int kt = 0; kt < NT; kt++) {
        uint32_t stage_off = (uint32_t)(kt & 1) * STAGE_BYTES;

        // ---- commit prefetched A (split to hi/lo) into smem ----
#pragma unroll
        for (int i = 0; i < 4; i++) {
            uint2 hi, lo;
            split4(apref[i], hi, lo);
            uint32_t so = a_row[i] * ROWB + a_j[i] * 8;
            *(uint2*)(smem + stage_off + 0 * ARR_BYTES + so) = hi;
            *(uint2*)(smem + stage_off + 1 * ARR_BYTES + so) = lo;
        }

        // ---- issue next tile's loads ----
        if (kt + 1 < NT) {
            load_B_stage(sb, (kt + 1) & 1, (kt + 1) * 32, bn, tid);
            CP_COMMIT();
            int kn = (kt + 1) * 32;
#pragma unroll
            for (int i = 0; i < 4; i++)
                apref[i] = load_concatA(x, bm + a_row[i], kn + a_j[i] * 4, N);
            CP_WAIT(1);
        } else {
            CP_WAIT(0);
        }
        __syncthreads();

        uint32_t sAhi = sb + stage_off + 0 * ARR_BYTES;
        uint32_t sAlo = sb + stage_off + 1 * ARR_BYTES;
        uint32_t sBhi = sb + stage_off + 2 * ARR_BYTES;
        uint32_t sBlo = sb + stage_off + 3 * ARR_BYTES;

#pragma unroll
        for (int ks = 0; ks < 32; ks += 16) {
            uint32_t afh[4][4], afl[4][4], bfh[2][4], bfl[2][4];
#pragma unroll
            for (int mi = 0; mi < 4; mi++) {
                uint32_t ao = (wm + mi * 16 + ld_row) * ROWB + (ks + ld_kb) * 2;
                LDMATRIX_X4(afh[mi], sAhi + ao);
                LDMATRIX_X4(afl[mi], sAlo + ao);
            }
#pragma unroll
            for (int bi = 0; bi < 2; bi++) {
                uint32_t bo = (wn + bi * 16 + ld_row) * ROWB + (ks + ld_kb) * 2;
                LDMATRIX_X4(bfh[bi], sBhi + bo);
                LDMATRIX_X4(bfl[bi], sBlo + bo);
            }
#pragma unroll
            for (int mi = 0; mi < 4; mi++) {
#pragma unroll
                for (int f = 0; f < 4; f++) {
                    int bi = f >> 1, od = f & 1;
                    uint32_t bh0 = bfh[bi][od], bh1 = bfh[bi][od + 2];
                    uint32_t bl0 = bfl[bi][od], bl1 = bfl[bi][od + 2];
                    mma_bf16(acc[mi][f], afh[mi], bh0, bh1);   // hi*hi
                    mma_bf16(acc[mi][f], afh[mi], bl0, bl1);   // hi*lo
                    mma_bf16(acc[mi][f], afl[mi], bh0, bh1);   // lo*hi
                }
            }
        }
        __syncthreads();
    }

    // ---- epilogue: c frag (row=lane/4 [+8], col=(lane%4)*2 [+1]) + bias ----
    int crow = lane >> 2, ccol = (lane & 3) * 2;
#pragma unroll
    for (int f = 0; f < 4; f++) {
        int n = bn + wn + f * 8 + ccol;
        float b0 = __ldg(bias + n), b1 = __ldg(bias + n + 1);
#pragma unroll
        for (int mi = 0; mi < 4; mi++) {
            int m0 = bm + wm + mi * 16 + crow;
            if (m0 < N) {
                float2 o0 = make_float2(acc[mi][f][0] + b0, acc[mi][f][1] + b1);
                *(float2*)(out + (size_t)m0 * OUT_CH + n) = o0;
            }
            int m1 = m0 + 8;
            if (m1 < N) {
                float2 o1 = make_float2(acc[mi][f][2] + b0, acc[mi][f][3] + b1);
                *(float2*)(out + (size_t)m1 * OUT_CH + n) = o1;
            }
        }
    }
}

// ================= launch =================
extern "C" void kernel_launch(void* const* d_in, const int* in_sizes, int n_in,
                              void* d_out, int out_size) {
    const float* x    = (const float*)d_in[0];
    const int*   ei   = (const int*)d_in[1];
    const float* W    = (const float*)d_in[2];
    const float* bias = (const float*)d_in[3];
    float*       out  = (float*)d_out;

    int N = in_sizes[0] / IN_CH;
    int E = in_sizes[1] / 2;
    if (N <= 0 || N > MAX_N || E <= 0 || E > MAX_E) return;
    const int* src = ei;
    const int* dst = ei + E;
    int mpad = ((N + 127) / 128) * 128;

    zero_count_kernel<<<(N + 255) / 256, 256>>>(N);
    hist_kernel<<<(E + 255) / 256, 256>>>(dst, E, N);
    scan_kernel<<<1, 1024>>>(N);
    scatter_kernel<<<(E + 255) / 256, 256>>>(src, dst, E, N);

    convert_w_kernel<<<(OUT_CH * 256 + 255) / 256, 256>>>(W);
    aggregate_kernel<<<N, 128>>>(x);

    cudaFuncSetAttribute(gemm_mma_kernel, cudaFuncAttributeMaxDynamicSharedMemorySize, GSMEM_TOTAL);
    dim3 grid(mpad / 128, OUT_CH / 128);
    gemm_mma_kernel<<<grid, 256, GSMEM_TOTAL>>>(x, bias, out, N);
}